// round 1
// baseline (speedup 1.0000x reference)
#include <cuda_runtime.h>

#define NN 8192
#define DD 64
#define EPSF 1e-6f

// scratch (no allocations allowed)
__device__ double g_acc;
__device__ float g_pi[NN];   // sq_i + 2*eps*s_i + D*eps^2
__device__ float g_qj[NN];   // sq_j - 2*eps*s_j

// ---------------------------------------------------------------------------
// prep: per-row sum / sum-of-squares of Z, plus zero the accumulator.
// one warp per row (lane loads 2 floats), warp shuffle reduce.
// ---------------------------------------------------------------------------
__global__ void prep_kernel(const float* __restrict__ Z) {
    if (blockIdx.x == 0 && threadIdx.x == 0) g_acc = 0.0;
    int w = (blockIdx.x * blockDim.x + threadIdx.x) >> 5;
    int lane = threadIdx.x & 31;
    if (w >= NN) return;
    float2 v = ((const float2*)(Z + (size_t)w * DD))[lane];
    float s = v.x + v.y;
    float sq = v.x * v.x + v.y * v.y;
#pragma unroll
    for (int off = 16; off; off >>= 1) {
        s  += __shfl_xor_sync(0xffffffffu, s, off);
        sq += __shfl_xor_sync(0xffffffffu, sq, off);
    }
    if (lane == 0) {
        g_pi[w] = sq + 2.0f * EPSF * s + (float)DD * EPSF * EPSF;
        g_qj[w] = sq - 2.0f * EPSF * s;
    }
}

// ---------------------------------------------------------------------------
// main: fused gram + distance + softplus + masked reduction.
// 64x64 output tile per block, 256 threads, 4x4 register micro-tile.
// Shared tiles stored transposed [k][row] with a float4-group XOR swizzle
// (group ^ ((k>>2)&7)) so the transpose STS is ~2-way instead of 16-way
// conflicted, while mainloop LDS.128 stays conflict-free.
// ---------------------------------------------------------------------------
__global__ __launch_bounds__(256) void lsm_main(const int* __restrict__ A,
                                                const float* __restrict__ alpha,
                                                const float* __restrict__ Z) {
    __shared__ float sA[64 * 64];   // Zi^T swizzled: [k][i]
    __shared__ float sB[64 * 64];   // Zj^T swizzled: [k][j]
    __shared__ float wsum[8];

    const int bi = blockIdx.y, bj = blockIdx.x;
    const int tid = (int)threadIdx.x;
    const int tx = tid & 15, ty = tid >> 4;

    // cooperative load + transpose + swizzle of both tiles
#pragma unroll
    for (int t = 0; t < 2; ++t) {
        const float* src = Z + (size_t)((t == 0 ? bi : bj) * 64) * DD;
        float* dst = (t == 0) ? sA : sB;
#pragma unroll
        for (int it = 0; it < 4; ++it) {
            int idx = it * 256 + tid;
            int r = idx >> 4;        // row within tile (i or j index)
            int k4 = idx & 15;       // float4 index along D
            float4 v = ((const float4*)(src + (size_t)r * DD))[k4];
#pragma unroll
            for (int c = 0; c < 4; ++c) {
                int k = k4 * 4 + c;
                int pg = (r >> 2) ^ ((k >> 2) & 7);   // swizzled float4-group
                dst[k * 64 + pg * 4 + (r & 3)] = ((const float*)&v)[c];
            }
        }
    }
    __syncthreads();

    float acc[4][4];
#pragma unroll
    for (int a = 0; a < 4; ++a)
#pragma unroll
        for (int b = 0; b < 4; ++b) acc[a][b] = 0.0f;

#pragma unroll 16
    for (int k = 0; k < 64; ++k) {
        int sw = (k >> 2) & 7;
        float4 av = *(const float4*)&sA[k * 64 + ((ty ^ sw) << 2)];
        float4 bv = *(const float4*)&sB[k * 64 + ((tx ^ sw) << 2)];
        const float* ap = (const float*)&av;
        const float* bp = (const float*)&bv;
#pragma unroll
        for (int ii = 0; ii < 4; ++ii)
#pragma unroll
            for (int jj = 0; jj < 4; ++jj)
                acc[ii][jj] = fmaf(ap[ii], bp[jj], acc[ii][jj]);
    }

    // epilogue
    const float4 pi4 = *(const float4*)&g_pi[bi * 64 + ty * 4];
    const float4 qj4 = *(const float4*)&g_qj[bj * 64 + tx * 4];
    const float4 al4 = *(const float4*)&alpha[bj * 64 + tx * 4];
    const float* pip = (const float*)&pi4;
    const float* qjp = (const float*)&qj4;
    const float* alp = (const float*)&al4;

    float ll = 0.0f;
#pragma unroll
    for (int ii = 0; ii < 4; ++ii) {
        int ig = bi * 64 + ty * 4 + ii;
        int4 a4 = *(const int4*)&A[(size_t)ig * NN + (bj * 64 + tx * 4)];
        const int* ap4 = (const int*)&a4;
        float pi = pip[ii];
#pragma unroll
        for (int jj = 0; jj < 4; ++jj) {
            int jg = bj * 64 + tx * 4 + jj;
            float d2 = fmaf(-2.0f, acc[ii][jj], pi + qjp[jj]);
            // sqrt via rsqrt (pure MUFU, zero-guarded for the diagonal)
            float zd = (d2 > 0.0f) ? d2 * rsqrtf(d2) : 0.0f;
            float th = alp[jj] - zd;
            float sp = __logf(1.0f + __expf(th));
            float spw = (ig == jg) ? 0.0f : sp;     // exclude diagonal softplus
            ll += (ap4[jj] ? th : 0.0f) - spw;
        }
    }
    ll *= 0.5f;

    // block reduction -> one double atomic per block
#pragma unroll
    for (int off = 16; off; off >>= 1) ll += __shfl_xor_sync(0xffffffffu, ll, off);
    if ((tid & 31) == 0) wsum[tid >> 5] = ll;
    __syncthreads();
    if (tid == 0) {
        float bsum = 0.0f;
#pragma unroll
        for (int w = 0; w < 8; ++w) bsum += wsum[w];
        atomicAdd(&g_acc, (double)bsum);
    }
}

__global__ void finish_kernel(float* out) { out[0] = (float)g_acc; }

// ---------------------------------------------------------------------------
extern "C" void kernel_launch(void* const* d_in, const int* in_sizes, int n_in,
                              void* d_out, int out_size) {
    const int* A = nullptr;
    const float* alpha = nullptr;
    const float* Z = nullptr;
    for (int i = 0; i < n_in; ++i) {
        if (in_sizes[i] == NN) alpha = (const float*)d_in[i];
        else if (in_sizes[i] == NN * DD) Z = (const float*)d_in[i];
        else A = (const int*)d_in[i];
    }

    prep_kernel<<<(NN * 32 + 255) / 256, 256>>>(Z);
    dim3 grid(NN / 64, NN / 64);
    lsm_main<<<grid, 256>>>(A, alpha, Z);
    finish_kernel<<<1, 1>>>((float*)d_out);
}

// round 3
// speedup vs baseline: 1.7753x; 1.7753x over previous
#include <cuda_runtime.h>
#include <cstdint>

#define NN 8192
#define DD 64
#define EPSF 1e-6f
#define PITCH 68   // floats; 68%32=4 -> conflict-free fragment loads, float4-aligned

// scratch (no allocations allowed)
__device__ double g_acc;
__device__ float g_pi[NN];    // sq_i + 2*eps*s_i + D*eps^2
__device__ float g_qa[NN*2];  // interleaved: (sq_j - 2*eps*s_j, alpha_j)

// ---------------------------------------------------------------------------
// prep: per-row sum / sum-of-squares of Z; zero accumulator; pack (qj,alpha).
// ---------------------------------------------------------------------------
__global__ void prep_kernel(const float* __restrict__ Z,
                            const float* __restrict__ alpha) {
    if (blockIdx.x == 0 && threadIdx.x == 0) g_acc = 0.0;
    int w = (blockIdx.x * blockDim.x + threadIdx.x) >> 5;
    int lane = threadIdx.x & 31;
    if (w >= NN) return;
    float2 v = ((const float2*)(Z + (size_t)w * DD))[lane];
    float s = v.x + v.y;
    float sq = v.x * v.x + v.y * v.y;
#pragma unroll
    for (int off = 16; off; off >>= 1) {
        s  += __shfl_xor_sync(0xffffffffu, s, off);
        sq += __shfl_xor_sync(0xffffffffu, sq, off);
    }
    if (lane == 0) {
        g_pi[w] = sq + 2.0f * EPSF * s + (float)DD * EPSF * EPSF;
        g_qa[2 * w]     = sq - 2.0f * EPSF * s;
        g_qa[2 * w + 1] = alpha[w];
    }
}

__device__ __forceinline__ uint32_t f2tf32(float f) {
    uint32_t u;
    asm("cvt.rna.tf32.f32 %0, %1;" : "=r"(u) : "f"(f));
    return u;
}

// ---------------------------------------------------------------------------
// main: tf32 mma.sync gram (tile 128 x 64, K=64) + fused epilogue.
// 128 threads (4 warps); warp computes 32(M) x 64(N) via m16n8k8 tf32 MMA.
// ---------------------------------------------------------------------------
__global__ __launch_bounds__(128) void lsm_main(const int* __restrict__ A,
                                                const float* __restrict__ Z) {
    extern __shared__ __align__(16) float smem[];
    float* s_zi = smem;                      // [128][PITCH] tf32 bits
    float* s_zj = smem + 128 * PITCH;        // [64][PITCH]
    float* s_pi = s_zj + 64 * PITCH;         // [128]
    float* s_qa = s_pi + 128;                // [64] float2 -> 128 floats
    float* s_ws = s_qa + 128;                // [4]

    const int tid = (int)threadIdx.x;
    const int wid = tid >> 5, lane = tid & 31;
    const int g = lane >> 2, t = lane & 3;   // groupID / thread-in-group
    const int bi = blockIdx.y, bj = blockIdx.x;   // tile: rows bi*128, cols bj*64

    // ---- stage small arrays ----
    s_pi[tid] = g_pi[bi * 128 + tid];
    if (tid < 64) ((float2*)s_qa)[tid] = ((const float2*)g_qa)[bj * 64 + tid];

    // ---- stage Z tiles (convert to tf32 bits at store) ----
    {
        const float4* src = (const float4*)(Z + (size_t)(bi * 128) * DD);
#pragma unroll
        for (int it = 0; it < 16; ++it) {
            int idx = it * 128 + tid;          // 2048 float4s
            int r = idx >> 4, k4 = idx & 15;
            float4 v = src[(size_t)r * 16 + k4];
            float* d = s_zi + r * PITCH + k4 * 4;
            d[0] = __uint_as_float(f2tf32(v.x));
            d[1] = __uint_as_float(f2tf32(v.y));
            d[2] = __uint_as_float(f2tf32(v.z));
            d[3] = __uint_as_float(f2tf32(v.w));
        }
        const float4* srcj = (const float4*)(Z + (size_t)(bj * 64) * DD);
#pragma unroll
        for (int it = 0; it < 8; ++it) {
            int idx = it * 128 + tid;          // 1024 float4s
            int r = idx >> 4, k4 = idx & 15;
            float4 v = srcj[(size_t)r * 16 + k4];
            float* d = s_zj + r * PITCH + k4 * 4;
            d[0] = __uint_as_float(f2tf32(v.x));
            d[1] = __uint_as_float(f2tf32(v.y));
            d[2] = __uint_as_float(f2tf32(v.z));
            d[3] = __uint_as_float(f2tf32(v.w));
        }
    }
    __syncthreads();

    // ---- gram: warp tile 32x64 (2 m-frags x 8 n-frags), K=64 in 8 steps ----
    float acc[2][8][4];
#pragma unroll
    for (int mf = 0; mf < 2; ++mf)
#pragma unroll
        for (int nf = 0; nf < 8; ++nf)
#pragma unroll
            for (int e = 0; e < 4; ++e) acc[mf][nf][e] = 0.0f;

    const int wm = wid * 32;                  // warp row base within tile
    const uint32_t* zi_u = (const uint32_t*)s_zi;
    const uint32_t* zj_u = (const uint32_t*)s_zj;

#pragma unroll
    for (int ks = 0; ks < 8; ++ks) {
        const int k0 = ks * 8;
        uint32_t a[2][4], b[8][2];
#pragma unroll
        for (int mf = 0; mf < 2; ++mf) {
            int r0 = wm + mf * 16 + g;
            a[mf][0] = zi_u[r0 * PITCH + k0 + t];
            a[mf][1] = zi_u[(r0 + 8) * PITCH + k0 + t];
            a[mf][2] = zi_u[r0 * PITCH + k0 + t + 4];
            a[mf][3] = zi_u[(r0 + 8) * PITCH + k0 + t + 4];
        }
#pragma unroll
        for (int nf = 0; nf < 8; ++nf) {
            int c0 = nf * 8 + g;
            b[nf][0] = zj_u[c0 * PITCH + k0 + t];
            b[nf][1] = zj_u[c0 * PITCH + k0 + t + 4];
        }
#pragma unroll
        for (int mf = 0; mf < 2; ++mf)
#pragma unroll
            for (int nf = 0; nf < 8; ++nf) {
                asm volatile(
                    "mma.sync.aligned.m16n8k8.row.col.f32.tf32.tf32.f32 "
                    "{%0,%1,%2,%3}, {%4,%5,%6,%7}, {%8,%9}, {%0,%1,%2,%3};"
                    : "+f"(acc[mf][nf][0]), "+f"(acc[mf][nf][1]),
                      "+f"(acc[mf][nf][2]), "+f"(acc[mf][nf][3])
                    : "r"(a[mf][0]), "r"(a[mf][1]), "r"(a[mf][2]), "r"(a[mf][3]),
                      "r"(b[nf][0]), "r"(b[nf][1]));
            }
    }

    // ---- fused epilogue ----
    // d-frag element (mf, rsel, nf, csel): i_loc = wm+mf*16+rsel*8+g,
    // j_loc = nf*8+2t+csel. A read: aligned int2 per (mf,rsel,nf).
    float ll = 0.0f;
#pragma unroll
    for (int mf = 0; mf < 2; ++mf) {
#pragma unroll
        for (int rsel = 0; rsel < 2; ++rsel) {
            int i_loc = wm + mf * 16 + rsel * 8 + g;
            int ig = bi * 128 + i_loc;
            float pi = s_pi[i_loc];
            const int2* arow = (const int2*)(A + (size_t)ig * NN + bj * 64);
#pragma unroll
            for (int nf = 0; nf < 8; ++nf) {
                int j0 = nf * 8 + 2 * t;
                int2 a2 = arow[nf * 4 + t];
                float2 qa0 = ((const float2*)s_qa)[j0];
                float2 qa1 = ((const float2*)s_qa)[j0 + 1];
#pragma unroll
                for (int c = 0; c < 2; ++c) {
                    float2 qa = c ? qa1 : qa0;
                    int av = c ? a2.y : a2.x;
                    int jg = bj * 64 + j0 + c;
                    float gv = acc[mf][nf][rsel * 2 + c];
                    float d2 = fmaf(-2.0f, gv, pi + qa.x);
                    float zd = (d2 > 0.0f) ? d2 * rsqrtf(d2) : 0.0f;
                    float th = qa.y - zd;
                    float sp = __logf(1.0f + __expf(th));
                    if (ig == jg) sp = 0.0f;           // exclude diagonal
                    ll += (av ? th : 0.0f) - sp;
                }
            }
        }
    }
    ll *= 0.5f;

    // ---- reduce + single double atomic per block ----
#pragma unroll
    for (int off = 16; off; off >>= 1) ll += __shfl_xor_sync(0xffffffffu, ll, off);
    if (lane == 0) s_ws[wid] = ll;
    __syncthreads();
    if (tid == 0)
        atomicAdd(&g_acc, (double)(s_ws[0] + s_ws[1] + s_ws[2] + s_ws[3]));
}

__global__ void finish_kernel(float* out) { out[0] = (float)g_acc; }

// ---------------------------------------------------------------------------
extern "C" void kernel_launch(void* const* d_in, const int* in_sizes, int n_in,
                              void* d_out, int out_size) {
    const int* A = nullptr;
    const float* alpha = nullptr;
    const float* Z = nullptr;
    for (int i = 0; i < n_in; ++i) {
        if (in_sizes[i] == NN) alpha = (const float*)d_in[i];
        else if (in_sizes[i] == NN * DD) Z = (const float*)d_in[i];
        else A = (const int*)d_in[i];
    }

    const int smem_bytes = (128 * PITCH + 64 * PITCH + 128 + 128 + 4) * 4;
    cudaFuncSetAttribute(lsm_main, cudaFuncAttributeMaxDynamicSharedMemorySize,
                         smem_bytes);

    prep_kernel<<<(NN * 32 + 255) / 256, 256>>>(Z, alpha);
    dim3 grid(NN / 64, NN / 128);
    lsm_main<<<grid, 128, smem_bytes>>>(A, Z);
    finish_kernel<<<1, 1>>>((float*)d_out);
}

// round 4
// speedup vs baseline: 1.9867x; 1.1191x over previous
#include <cuda_runtime.h>
#include <cstdint>

#define NN 8192
#define DD 64
#define EPSF 1e-6f
#define PITCH 68     // floats; conflict-free fragment loads, float4-aligned
#define T_U 0.0625f  // log1p poly valid below this (abs err < 4e-6)

// scratch (no allocations allowed)
__device__ double g_acc;
__device__ float g_pi[NN];    // sq_i + 2*eps*s_i + D*eps^2   (EXACT fp32)
__device__ float g_qa[NN*2];  // interleaved: (sq_j - 2*eps*s_j, alpha_j)

// ---------------------------------------------------------------------------
__global__ void prep_kernel(const float* __restrict__ Z,
                            const float* __restrict__ alpha) {
    if (blockIdx.x == 0 && threadIdx.x == 0) g_acc = 0.0;
    int w = (blockIdx.x * blockDim.x + threadIdx.x) >> 5;
    int lane = threadIdx.x & 31;
    if (w >= NN) return;
    float2 v = ((const float2*)(Z + (size_t)w * DD))[lane];
    float s = v.x + v.y;
    float sq = v.x * v.x + v.y * v.y;
#pragma unroll
    for (int off = 16; off; off >>= 1) {
        s  += __shfl_xor_sync(0xffffffffu, s, off);
        sq += __shfl_xor_sync(0xffffffffu, sq, off);
    }
    if (lane == 0) {
        g_pi[w] = sq + 2.0f * EPSF * s + (float)DD * EPSF * EPSF;
        g_qa[2 * w]     = sq - 2.0f * EPSF * s;
        g_qa[2 * w + 1] = alpha[w];
    }
}

__device__ __forceinline__ uint32_t f2tf32(float f) {
    uint32_t u;
    asm("cvt.rna.tf32.f32 %0, %1;" : "=r"(u) : "f"(f));
    return u;
}

__device__ __forceinline__ float sqrt_approx(float x) {
    float r;
    asm("sqrt.approx.f32 %0, %1;" : "=f"(r) : "f"(x));
    return r;
}

__device__ __forceinline__ float log1p_poly(float u) {
    // u - u^2/2 + u^3/3
    return u * fmaf(u, fmaf(u, 0.33333333f, -0.5f), 1.0f);
}

// ---------------------------------------------------------------------------
// main: tf32 mma.sync gram (tile 128 x 64, K=64) + pipelined fused epilogue.
// 128 threads (4 warps); warp tile 32(M) x 64(N); nf-outer: MMA(nf) overlaps
// epilogue(nf-1).
// ---------------------------------------------------------------------------
__global__ __launch_bounds__(128) void lsm_main(const int* __restrict__ A,
                                                const float* __restrict__ Z) {
    extern __shared__ __align__(16) float smem[];
    float* s_zi = smem;                      // [128][PITCH] tf32 bits
    float* s_zj = smem + 128 * PITCH;        // [64][PITCH]
    float* s_pi = s_zj + 64 * PITCH;         // [128]
    float* s_qa = s_pi + 128;                // 64 float2
    float* s_ws = s_qa + 128;                // [4]

    const int tid = (int)threadIdx.x;
    const int wid = tid >> 5, lane = tid & 31;
    const int g = lane >> 2, t = lane & 3;
    const int bi = blockIdx.y, bj = blockIdx.x;   // rows bi*128, cols bj*64
    const int wm = wid * 32;
    const bool diagblk = ((bj >> 1) == bi);

    // ---- stage small arrays ----
    s_pi[tid] = g_pi[bi * 128 + tid];
    if (tid < 64) ((float2*)s_qa)[tid] = ((const float2*)g_qa)[bj * 64 + tid];

    // ---- stage Z tiles (tf32 truncation at store) ----
    {
        const float4* src = (const float4*)(Z + (size_t)(bi * 128) * DD);
#pragma unroll
        for (int it = 0; it < 16; ++it) {
            int idx = it * 128 + tid;
            int r = idx >> 4, k4 = idx & 15;
            float4 v = src[(size_t)r * 16 + k4];
            float* d = s_zi + r * PITCH + k4 * 4;
            d[0] = __uint_as_float(f2tf32(v.x));
            d[1] = __uint_as_float(f2tf32(v.y));
            d[2] = __uint_as_float(f2tf32(v.z));
            d[3] = __uint_as_float(f2tf32(v.w));
        }
        const float4* srcj = (const float4*)(Z + (size_t)(bj * 64) * DD);
#pragma unroll
        for (int it = 0; it < 8; ++it) {
            int idx = it * 128 + tid;
            int r = idx >> 4, k4 = idx & 15;
            float4 v = srcj[(size_t)r * 16 + k4];
            float* d = s_zj + r * PITCH + k4 * 4;
            d[0] = __uint_as_float(f2tf32(v.x));
            d[1] = __uint_as_float(f2tf32(v.y));
            d[2] = __uint_as_float(f2tf32(v.z));
            d[3] = __uint_as_float(f2tf32(v.w));
        }
    }
    __syncthreads();

    const uint32_t* zi_u = (const uint32_t*)s_zi;
    const uint32_t* zj_u = (const uint32_t*)s_zj;
    const float2* qaf2 = (const float2*)s_qa;

    // ---- preload ALL a-fragments (K=64) into registers ----
    uint32_t a[8][2][4];
#pragma unroll
    for (int ks = 0; ks < 8; ++ks) {
        const int k0 = ks * 8;
#pragma unroll
        for (int mf = 0; mf < 2; ++mf) {
            int r0 = wm + mf * 16 + g;
            a[ks][mf][0] = zi_u[r0 * PITCH + k0 + t];
            a[ks][mf][1] = zi_u[(r0 + 8) * PITCH + k0 + t];
            a[ks][mf][2] = zi_u[r0 * PITCH + k0 + t + 4];
            a[ks][mf][3] = zi_u[(r0 + 8) * PITCH + k0 + t + 4];
        }
    }

    // per-thread row constants
    float pir[4];
    const int2* ar[4];
#pragma unroll
    for (int mf = 0; mf < 2; ++mf)
#pragma unroll
        for (int rs = 0; rs < 2; ++rs) {
            int r = mf * 2 + rs;
            int i_loc = wm + mf * 16 + rs * 8 + g;
            pir[r] = s_pi[i_loc];
            ar[r] = (const int2*)(A + (size_t)(bi * 128 + i_loc) * NN + bj * 64);
        }

    float ll = 0.0f;
    float acc0[2][4], acc1[2][4];

    // ---- MMA for one n-group ----
#define DO_MMA(NF, ACC)                                                        \
    do {                                                                       \
        _Pragma("unroll")                                                      \
        for (int mf = 0; mf < 2; ++mf)                                         \
            _Pragma("unroll")                                                  \
            for (int e = 0; e < 4; ++e) ACC[mf][e] = 0.0f;                     \
        _Pragma("unroll")                                                      \
        for (int ks = 0; ks < 8; ++ks) {                                       \
            int c0 = (NF) * 8 + g;                                             \
            uint32_t b0 = zj_u[c0 * PITCH + ks * 8 + t];                       \
            uint32_t b1 = zj_u[c0 * PITCH + ks * 8 + t + 4];                   \
            _Pragma("unroll")                                                  \
            for (int mf = 0; mf < 2; ++mf) {                                   \
                asm volatile(                                                  \
                    "mma.sync.aligned.m16n8k8.row.col.f32.tf32.tf32.f32 "      \
                    "{%0,%1,%2,%3}, {%4,%5,%6,%7}, {%8,%9}, {%0,%1,%2,%3};"    \
                    : "+f"(ACC[mf][0]), "+f"(ACC[mf][1]),                      \
                      "+f"(ACC[mf][2]), "+f"(ACC[mf][3])                       \
                    : "r"(a[ks][mf][0]), "r"(a[ks][mf][1]),                    \
                      "r"(a[ks][mf][2]), "r"(a[ks][mf][3]),                    \
                      "r"(b0), "r"(b1));                                       \
            }                                                                  \
        }                                                                      \
    } while (0)

    // ---- epilogue for one n-group ----
#define DO_EPI(NF, ACC)                                                        \
    do {                                                                       \
        float u[8];                                                            \
        float2 qa0 = qaf2[(NF) * 8 + 2 * t];                                   \
        float2 qa1 = qaf2[(NF) * 8 + 2 * t + 1];                               \
        bool slow = false;                                                     \
        _Pragma("unroll")                                                      \
        for (int mf = 0; mf < 2; ++mf)                                         \
            _Pragma("unroll")                                                  \
            for (int rs = 0; rs < 2; ++rs) {                                   \
                int r = mf * 2 + rs;                                           \
                int2 a2 = ar[r][(NF) * 4 + t];                                 \
                _Pragma("unroll")                                              \
                for (int c = 0; c < 2; ++c) {                                  \
                    int e = r * 2 + c;                                         \
                    float2 q = c ? qa1 : qa0;                                  \
                    float d2 = fmaf(-2.0f, ACC[mf][rs * 2 + c], pir[r] + q.x); \
                    float zd = sqrt_approx(fmaxf(d2, 0.0f));                   \
                    float th = q.y - zd;                                       \
                    float uu = __expf(th);                                     \
                    u[e] = uu;                                                 \
                    slow = slow || (uu > T_U);                                 \
                    float af = (float)(c ? a2.y : a2.x);                       \
                    ll += fmaf(af, th, -log1p_poly(uu));                       \
                }                                                              \
            }                                                                  \
        if (__any_sync(0xffffffffu, slow)) {                                   \
            _Pragma("unroll")                                                  \
            for (int e = 0; e < 8; ++e)                                        \
                if (u[e] > T_U)                                                \
                    ll += log1p_poly(u[e]) - __logf(1.0f + u[e]);              \
        }                                                                      \
        if (diagblk) {                                                         \
            _Pragma("unroll")                                                  \
            for (int mf = 0; mf < 2; ++mf)                                     \
                _Pragma("unroll")                                              \
                for (int rs = 0; rs < 2; ++rs)                                 \
                    _Pragma("unroll")                                          \
                    for (int c = 0; c < 2; ++c) {                              \
                        int e = (mf * 2 + rs) * 2 + c;                         \
                        int ig = bi * 128 + wm + mf * 16 + rs * 8 + g;         \
                        int jg = bj * 64 + (NF) * 8 + 2 * t + c;               \
                        if (ig == jg) {                                        \
                            float spv = (u[e] > T_U)                           \
                                            ? __logf(1.0f + u[e])              \
                                            : log1p_poly(u[e]);                \
                            ll += spv; /* cancel the subtracted softplus */    \
                        }                                                      \
                    }                                                          \
        }                                                                      \
    } while (0)

    // ---- skewed pipeline: MMA(nf) overlaps epilogue(nf-1) ----
    DO_MMA(0, acc0);
    DO_MMA(1, acc1);  DO_EPI(0, acc0);
    DO_MMA(2, acc0);  DO_EPI(1, acc1);
    DO_MMA(3, acc1);  DO_EPI(2, acc0);
    DO_MMA(4, acc0);  DO_EPI(3, acc1);
    DO_MMA(5, acc1);  DO_EPI(4, acc0);
    DO_MMA(6, acc0);  DO_EPI(5, acc1);
    DO_MMA(7, acc1);  DO_EPI(6, acc0);
    DO_EPI(7, acc1);

    ll *= 0.5f;

    // ---- reduce + single double atomic per block ----
#pragma unroll
    for (int off = 16; off; off >>= 1) ll += __shfl_xor_sync(0xffffffffu, ll, off);
    if (lane == 0) s_ws[wid] = ll;
    __syncthreads();
    if (tid == 0)
        atomicAdd(&g_acc, (double)(s_ws[0] + s_ws[1] + s_ws[2] + s_ws[3]));
}

__global__ void finish_kernel(float* out) { out[0] = (float)g_acc; }

// ---------------------------------------------------------------------------
extern "C" void kernel_launch(void* const* d_in, const int* in_sizes, int n_in,
                              void* d_out, int out_size) {
    const int* A = nullptr;
    const float* alpha = nullptr;
    const float* Z = nullptr;
    for (int i = 0; i < n_in; ++i) {
        if (in_sizes[i] == NN) alpha = (const float*)d_in[i];
        else if (in_sizes[i] == NN * DD) Z = (const float*)d_in[i];
        else A = (const int*)d_in[i];
    }

    const int smem_bytes = (128 * PITCH + 64 * PITCH + 128 + 128 + 4) * 4;
    cudaFuncSetAttribute(lsm_main, cudaFuncAttributeMaxDynamicSharedMemorySize,
                         smem_bytes);

    prep_kernel<<<(NN * 32 + 255) / 256, 256>>>(Z, alpha);
    dim3 grid(NN / 64, NN / 128);
    lsm_main<<<grid, 128, smem_bytes>>>(A, Z);
    finish_kernel<<<1, 1>>>((float*)d_out);
}

// round 5
// speedup vs baseline: 2.8987x; 1.4590x over previous
#include <cuda_runtime.h>
#include <cstdint>

#define NN 8192
#define DD 64
#define EPSF 1e-6f
#define PITCH_W 36   // 32-bit words per smem row (144B): 36%32=4 -> conflict-free
#define T_U 0.0625f  // log1p poly valid below this (abs err < 4e-6)

// scratch (no allocations allowed)
__device__ double g_acc;
__device__ float g_pi[NN];    // sq_i + 2*eps*s_i + D*eps^2   (EXACT fp32)
__device__ float g_qa[NN*2];  // interleaved: (sq_j - 2*eps*s_j, alpha_j)

// ---------------------------------------------------------------------------
__global__ void prep_kernel(const float* __restrict__ Z,
                            const float* __restrict__ alpha) {
    if (blockIdx.x == 0 && threadIdx.x == 0) g_acc = 0.0;
    int w = (blockIdx.x * blockDim.x + threadIdx.x) >> 5;
    int lane = threadIdx.x & 31;
    if (w >= NN) return;
    float2 v = ((const float2*)(Z + (size_t)w * DD))[lane];
    float s = v.x + v.y;
    float sq = v.x * v.x + v.y * v.y;
#pragma unroll
    for (int off = 16; off; off >>= 1) {
        s  += __shfl_xor_sync(0xffffffffu, s, off);
        sq += __shfl_xor_sync(0xffffffffu, sq, off);
    }
    if (lane == 0) {
        g_pi[w] = sq + 2.0f * EPSF * s + (float)DD * EPSF * EPSF;
        g_qa[2 * w]     = sq - 2.0f * EPSF * s;
        g_qa[2 * w + 1] = alpha[w];
    }
}

__device__ __forceinline__ uint32_t pack_bf16x2(float lo, float hi) {
    uint32_t r;  // upper half <- first source operand
    asm("cvt.rn.bf16x2.f32 %0, %1, %2;" : "=r"(r) : "f"(hi), "f"(lo));
    return r;
}

__device__ __forceinline__ float sqrt_approx(float x) {
    float r;
    asm("sqrt.approx.f32 %0, %1;" : "=f"(r) : "f"(x));
    return r;
}

__device__ __forceinline__ float log1p_poly(float u) {
    return u * fmaf(u, fmaf(u, 0.33333333f, -0.5f), 1.0f);
}

// ---------------------------------------------------------------------------
// main: bf16 mma.sync gram (tile 128 x 64, K=64) + pipelined fused epilogue.
// 128 threads (4 warps); warp tile 32(M) x 64(N); nf-outer skewed pipeline.
// ---------------------------------------------------------------------------
__global__ __launch_bounds__(128) void lsm_main(const int* __restrict__ A,
                                                const float* __restrict__ Z) {
    extern __shared__ __align__(16) uint32_t smem[];
    uint32_t* s_zi = smem;                       // [128][PITCH_W] bf16x2 words
    uint32_t* s_zj = smem + 128 * PITCH_W;       // [64][PITCH_W]
    float* s_pi = (float*)(s_zj + 64 * PITCH_W); // [128]
    float* s_qa = s_pi + 128;                    // 64 float2
    float* s_ws = s_qa + 128;                    // [4]

    const int tid = (int)threadIdx.x;
    const int wid = tid >> 5, lane = tid & 31;
    const int g = lane >> 2, t = lane & 3;
    const int bi = blockIdx.y, bj = blockIdx.x;   // rows bi*128, cols bj*64
    const int wm = wid * 32;
    const bool diagblk = ((bj >> 1) == bi);

    // ---- stage small arrays ----
    s_pi[tid] = g_pi[bi * 128 + tid];
    if (tid < 64) ((float2*)s_qa)[tid] = ((const float2*)g_qa)[bj * 64 + tid];

    // ---- stage Z tiles as bf16 (rn) ----
    {
        const float4* src = (const float4*)(Z + (size_t)(bi * 128) * DD);
#pragma unroll
        for (int it = 0; it < 16; ++it) {
            int idx = it * 128 + tid;          // 2048 float4s
            int r = idx >> 4, k4 = idx & 15;
            float4 v = src[(size_t)r * 16 + k4];
            uint2 p = make_uint2(pack_bf16x2(v.x, v.y), pack_bf16x2(v.z, v.w));
            *(uint2*)(s_zi + r * PITCH_W + k4 * 2) = p;
        }
        const float4* srcj = (const float4*)(Z + (size_t)(bj * 64) * DD);
#pragma unroll
        for (int it = 0; it < 8; ++it) {
            int idx = it * 128 + tid;          // 1024 float4s
            int r = idx >> 4, k4 = idx & 15;
            float4 v = srcj[(size_t)r * 16 + k4];
            uint2 p = make_uint2(pack_bf16x2(v.x, v.y), pack_bf16x2(v.z, v.w));
            *(uint2*)(s_zj + r * PITCH_W + k4 * 2) = p;
        }
    }
    __syncthreads();

    const float2* qaf2 = (const float2*)s_qa;

    // ---- preload ALL a-fragments (K=64 -> 4 k16-steps) ----
    uint32_t a[4][2][4];
#pragma unroll
    for (int ks = 0; ks < 4; ++ks) {
#pragma unroll
        for (int mf = 0; mf < 2; ++mf) {
            int r0 = wm + mf * 16 + g;
            const uint32_t* base = s_zi + ks * 8 + t;
            a[ks][mf][0] = base[r0 * PITCH_W];
            a[ks][mf][1] = base[(r0 + 8) * PITCH_W];
            a[ks][mf][2] = base[r0 * PITCH_W + 4];
            a[ks][mf][3] = base[(r0 + 8) * PITCH_W + 4];
        }
    }

    // per-thread row constants
    float pir[4];
    const int2* ar[4];
#pragma unroll
    for (int mf = 0; mf < 2; ++mf)
#pragma unroll
        for (int rs = 0; rs < 2; ++rs) {
            int r = mf * 2 + rs;
            int i_loc = wm + mf * 16 + rs * 8 + g;
            pir[r] = s_pi[i_loc];
            ar[r] = (const int2*)(A + (size_t)(bi * 128 + i_loc) * NN + bj * 64);
        }

    float ll = 0.0f;
    float acc0[2][4], acc1[2][4];

    // ---- MMA for one n-group: 4 k-steps x 2 m-frags of m16n8k16 bf16 ----
#define DO_MMA(NF, ACC)                                                        \
    do {                                                                       \
        _Pragma("unroll")                                                      \
        for (int mf = 0; mf < 2; ++mf)                                         \
            _Pragma("unroll")                                                  \
            for (int e = 0; e < 4; ++e) ACC[mf][e] = 0.0f;                     \
        _Pragma("unroll")                                                      \
        for (int ks = 0; ks < 4; ++ks) {                                       \
            int c0 = (NF) * 8 + g;                                             \
            uint32_t b0 = s_zj[c0 * PITCH_W + ks * 8 + t];                     \
            uint32_t b1 = s_zj[c0 * PITCH_W + ks * 8 + t + 4];                 \
            _Pragma("unroll")                                                  \
            for (int mf = 0; mf < 2; ++mf) {                                   \
                asm volatile(                                                  \
                    "mma.sync.aligned.m16n8k16.row.col.f32.bf16.bf16.f32 "     \
                    "{%0,%1,%2,%3}, {%4,%5,%6,%7}, {%8,%9}, {%0,%1,%2,%3};"    \
                    : "+f"(ACC[mf][0]), "+f"(ACC[mf][1]),                      \
                      "+f"(ACC[mf][2]), "+f"(ACC[mf][3])                       \
                    : "r"(a[ks][mf][0]), "r"(a[ks][mf][1]),                    \
                      "r"(a[ks][mf][2]), "r"(a[ks][mf][3]),                    \
                      "r"(b0), "r"(b1));                                       \
            }                                                                  \
        }                                                                      \
    } while (0)

    // ---- epilogue for one n-group ----
#define DO_EPI(NF, ACC)                                                        \
    do {                                                                       \
        float u[8];                                                            \
        float2 qa0 = qaf2[(NF) * 8 + 2 * t];                                   \
        float2 qa1 = qaf2[(NF) * 8 + 2 * t + 1];                               \
        bool slow = false;                                                     \
        _Pragma("unroll")                                                      \
        for (int mf = 0; mf < 2; ++mf)                                         \
            _Pragma("unroll")                                                  \
            for (int rs = 0; rs < 2; ++rs) {                                   \
                int r = mf * 2 + rs;                                           \
                int2 a2 = ar[r][(NF) * 4 + t];                                 \
                _Pragma("unroll")                                              \
                for (int c = 0; c < 2; ++c) {                                  \
                    int e = r * 2 + c;                                         \
                    float2 q = c ? qa1 : qa0;                                  \
                    float d2 = fmaf(-2.0f, ACC[mf][rs * 2 + c], pir[r] + q.x); \
                    float zd = sqrt_approx(fmaxf(d2, 0.0f));                   \
                    float th = q.y - zd;                                       \
                    float uu = __expf(th);                                     \
                    u[e] = uu;                                                 \
                    slow = slow || (uu > T_U);                                 \
                    float af = (float)(c ? a2.y : a2.x);                       \
                    ll += fmaf(af, th, -log1p_poly(uu));                       \
                }                                                              \
            }                                                                  \
        if (__any_sync(0xffffffffu, slow)) {                                   \
            _Pragma("unroll")                                                  \
            for (int e = 0; e < 8; ++e)                                        \
                if (u[e] > T_U)                                                \
                    ll += log1p_poly(u[e]) - __logf(1.0f + u[e]);              \
        }                                                                      \
        if (diagblk) {                                                         \
            _Pragma("unroll")                                                  \
            for (int mf = 0; mf < 2; ++mf)                                     \
                _Pragma("unroll")                                              \
                for (int rs = 0; rs < 2; ++rs)                                 \
                    _Pragma("unroll")                                          \
                    for (int c = 0; c < 2; ++c) {                              \
                        int e = (mf * 2 + rs) * 2 + c;                         \
                        int ig = bi * 128 + wm + mf * 16 + rs * 8 + g;         \
                        int jg = bj * 64 + (NF) * 8 + 2 * t + c;               \
                        if (ig == jg) {                                        \
                            float spv = (u[e] > T_U)                           \
                                            ? __logf(1.0f + u[e])              \
                                            : log1p_poly(u[e]);                \
                            ll += spv; /* cancel the subtracted softplus */    \
                        }                                                      \
                    }                                                          \
        }                                                                      \
    } while (0)

    // ---- skewed pipeline: MMA(nf) overlaps epilogue(nf-1) ----
    DO_MMA(0, acc0);
    DO_MMA(1, acc1);  DO_EPI(0, acc0);
    DO_MMA(2, acc0);  DO_EPI(1, acc1);
    DO_MMA(3, acc1);  DO_EPI(2, acc0);
    DO_MMA(4, acc0);  DO_EPI(3, acc1);
    DO_MMA(5, acc1);  DO_EPI(4, acc0);
    DO_MMA(6, acc0);  DO_EPI(5, acc1);
    DO_MMA(7, acc1);  DO_EPI(6, acc0);
    DO_EPI(7, acc1);

    ll *= 0.5f;

    // ---- reduce + single double atomic per block ----
#pragma unroll
    for (int off = 16; off; off >>= 1) ll += __shfl_xor_sync(0xffffffffu, ll, off);
    if (lane == 0) s_ws[wid] = ll;
    __syncthreads();
    if (tid == 0)
        atomicAdd(&g_acc, (double)(s_ws[0] + s_ws[1] + s_ws[2] + s_ws[3]));
}

__global__ void finish_kernel(float* out) { out[0] = (float)g_acc; }

// ---------------------------------------------------------------------------
extern "C" void kernel_launch(void* const* d_in, const int* in_sizes, int n_in,
                              void* d_out, int out_size) {
    const int* A = nullptr;
    const float* alpha = nullptr;
    const float* Z = nullptr;
    for (int i = 0; i < n_in; ++i) {
        if (in_sizes[i] == NN) alpha = (const float*)d_in[i];
        else if (in_sizes[i] == NN * DD) Z = (const float*)d_in[i];
        else A = (const int*)d_in[i];
    }

    const int smem_bytes = (128 * PITCH_W + 64 * PITCH_W + 128 + 128 + 4) * 4;
    cudaFuncSetAttribute(lsm_main, cudaFuncAttributeMaxDynamicSharedMemorySize,
                         smem_bytes);

    prep_kernel<<<(NN * 32 + 255) / 256, 256>>>(Z, alpha);
    dim3 grid(NN / 64, NN / 128);
    lsm_main<<<grid, 128, smem_bytes>>>(A, Z);
    finish_kernel<<<1, 1>>>((float*)d_out);
}